// round 9
// baseline (speedup 1.0000x reference)
#include <cuda_runtime.h>

// Problem constants
#define NC 4
#define NB 128
#define NG 2048
#define NS 32
#define NL 3
#define NBQ 4                 // 128 b-lanes split into 4 groups of 32
#define GPB 64                // g per block in kernel A
#define NWARPS 8
#define GPW (GPB/NWARPS)      // 8 g per warp
#define NTOT (NC*NB*NG)       // 1,048,576
#define BGTOT (NB*NG)         // 262,144 (= 2^18)
#define NIDX (NC*NG*NS*NL)    // 786,432 index entries

// Scratch (no allocation allowed -> device globals)
__device__ float d_Z[NTOT];            // valuation storage (bq layout)
__device__ float d_T[NTOT];            // clause_eval output  (bq layout)
__device__ float d_xq[BGTOT];          // transposed x (bq layout, shared by all c)
__device__ uint4 d_Ip4[NC*NG*12];      // packed uint16 indices: 96 per g = 12 uint4
__device__ unsigned int d_slots[8];    // float-as-uint max accumulators

__device__ __forceinline__ float slot_scale(int idx) {
    if (idx < 0) return 1.0f;
    float m = __uint_as_float(d_slots[idx]);
    return (m > 1.0f) ? (1.0f / m) : 1.0f;
}

// Gather with L1 evict-last policy: slab lines should stay resident in L1.
__device__ __forceinline__ float ldg_el(const float* p) {
    float v;
    asm("ld.global.L1::evict_last.f32 %0, [%1];" : "=f"(v) : "l"(p));
    return v;
}
// Streaming store: d_T is never re-read by this kernel; don't pollute L1.
__device__ __forceinline__ void stg_cs(float* p, float v) {
    asm volatile("st.global.cs.f32 [%0], %1;" :: "l"(p), "f"(v));
}

// Launch #1: zero the max slots (separate so launch #6 is a step-1 kernelA for ncu).
__global__ void zero_kernel() {
    if (threadIdx.x < 8) d_slots[threadIdx.x] = 0u;
}

// Pack int32 indices (< 2048) into uint16.
__global__ void pack_kernel(const int* __restrict__ I) {
    int i = blockIdx.x * blockDim.x + threadIdx.x;
    if (i < NIDX / 2) {
        int a = I[i * 2], b = I[i * 2 + 1];
        ((unsigned int*)d_Ip4)[i] = (unsigned)a | ((unsigned)b << 16);
    }
}

// Tiled transpose: xq[(bq*NG+g)*32 + lane] = x[(bq*32+lane)*NG + g], coalesced both ways.
__global__ void init_kernel(const float* __restrict__ x) {
    __shared__ float tile[32][33];
    const int g0 = blockIdx.x * 32, bq = blockIdx.y;
    const int lane = threadIdx.x, ty = threadIdx.y;   // block (32, 8)
    #pragma unroll
    for (int r = 0; r < 4; r++) {
        int bl = ty + r * 8;
        tile[bl][lane] = x[(bq * 32 + bl) * NG + g0 + lane];   // coalesced over g
    }
    __syncthreads();
    #pragma unroll
    for (int r = 0; r < 4; r++) {
        int gi = ty + r * 8;
        d_xq[(bq * NG + g0 + gi) * 32 + lane] = tile[lane][gi]; // coalesced over lane
    }
}

// Kernel A: T[c,b,g] = gamma*logsumexp_s( prod_l R[c,b,I[c,g,s,l]] / gamma )
// Online (chunked) logsumexp; evict-last gathers; streaming d_T stores.
__global__ void __launch_bounds__(256, 6) kernelA(int srcIsZ, int scaleIdx, int maxIdx) {
    __shared__ uint4 sIdx[GPB * 12];      // 64 g * 48B = 12KB
    __shared__ float sMax[NWARPS];
    const int c = blockIdx.z, bq = blockIdx.y;
    const int g0 = blockIdx.x * GPB;
    const int tid = threadIdx.x, lane = tid & 31, w = tid >> 5;

    // Stage this block's packed index tile (coalesced uint4) into shared
    const uint4* Ibase = d_Ip4 + (c * NG + g0) * 12;
    #pragma unroll
    for (int i = tid; i < GPB * 12; i += 256) sIdx[i] = Ibase[i];
    __syncthreads();

    const float s = slot_scale(scaleIdx);
    const float s3 = s * s * s;                  // scale folded into 3-way product
    const float c2 = s3 * 144.269504f;           // (1/gamma)*s3*log2(e)
    const float* __restrict__ slab =
        srcIsZ ? (d_Z + (c * NBQ + bq) * (NG * 32)) : (d_xq + bq * (NG * 32));

    float wmax = 0.0f;
    #pragma unroll 1
    for (int gi = 0; gi < GPW; gi++) {
        const int gl = w * GPW + gi;
        const uint4* ip4 = sIdx + gl * 12;
        float m = 0.0f, ssum = 0.0f;             // online LSE state (products >= 0)
        #pragma unroll 1
        for (int ch = 0; ch < 4; ch++) {         // 8 substitutions per chunk
            uint4 w0 = ip4[ch * 3 + 0];
            uint4 w1 = ip4[ch * 3 + 1];
            uint4 w2 = ip4[ch * 3 + 2];
            unsigned u[12] = {w0.x, w0.y, w0.z, w0.w,
                              w1.x, w1.y, w1.z, w1.w,
                              w2.x, w2.y, w2.z, w2.w};
            float p[8];
            float cmax = 0.0f;
            #pragma unroll
            for (int j = 0; j < 8; j++) {
                int k0 = 3 * j, k1 = 3 * j + 1, k2 = 3 * j + 2;
                unsigned i0 = (u[k0 >> 1] >> ((k0 & 1) * 16)) & 0xffffu;
                unsigned i1 = (u[k1 >> 1] >> ((k1 & 1) * 16)) & 0xffffu;
                unsigned i2 = (u[k2 >> 1] >> ((k2 & 1) * 16)) & 0xffffu;
                float v0 = ldg_el(slab + (i0 << 5) + lane);   // 128B warp-coalesced
                float v1 = ldg_el(slab + (i1 << 5) + lane);
                float v2 = ldg_el(slab + (i2 << 5) + lane);
                float pp = v0 * v1 * v2;
                p[j] = pp;
                cmax = fmaxf(cmax, pp);
            }
            float mn = fmaxf(m, cmax);
            float acc = ssum * exp2f((m - mn) * c2);
            float e0 = exp2f((p[0] - mn) * c2) + exp2f((p[1] - mn) * c2);
            float e1 = exp2f((p[2] - mn) * c2) + exp2f((p[3] - mn) * c2);
            float e2 = exp2f((p[4] - mn) * c2) + exp2f((p[5] - mn) * c2);
            float e3 = exp2f((p[6] - mn) * c2) + exp2f((p[7] - mn) * c2);
            ssum = acc + ((e0 + e1) + (e2 + e3));
            m = mn;
        }
        float t = fmaf(0.0069314718f, __log2f(ssum), m * s3);   // gamma*ln2*log2
        stg_cs(d_T + ((c * NBQ + bq) * NG + g0 + gl) * 32 + lane, t);
        wmax = fmaxf(wmax, t);
    }
    #pragma unroll
    for (int o = 16; o; o >>= 1) wmax = fmaxf(wmax, __shfl_xor_sync(0xffffffffu, wmax, o));
    if (lane == 0) sMax[w] = wmax;
    __syncthreads();
    if (tid == 0) {
        float bm = sMax[0];
        #pragma unroll
        for (int k = 1; k < NWARPS; k++) bm = fmaxf(bm, sMax[k]);
        atomicMax(&d_slots[maxIdx], __float_as_uint(bm));
    }
}

// Kernel B: Z = softor2(R, T') elementwise, 4 elems/thread via float4.
__global__ void __launch_bounds__(256) kernelB(int srcIsZ, int rIdx, int tIdx, int maxIdx) {
    __shared__ float sMax[8];
    const int i = blockIdx.x * 256 + threadIdx.x;        // float4 index
    const float sr = slot_scale(rIdx);
    const float st = slot_scale(tIdx);
    float4 rv = srcIsZ ? ((const float4*)d_Z)[i]
                       : ((const float4*)d_xq)[i & (BGTOT / 4 - 1)];
    float4 tv = ((const float4*)d_T)[i];
    float zr[4];
    const float r4[4] = {rv.x, rv.y, rv.z, rv.w};
    const float t4[4] = {tv.x, tv.y, tv.z, tv.w};
    float wm = 0.0f;
    #pragma unroll
    for (int j = 0; j < 4; j++) {
        float r = r4[j] * sr, t = t4[j] * st;
        float mx = fmaxf(r, t), mn = fminf(r, t);
        float z = fmaf(0.0069314718f,
                       __log2f(1.0f + exp2f((mn - mx) * 144.269504f)), mx);
        zr[j] = z;
        wm = fmaxf(wm, z);
    }
    ((float4*)d_Z)[i] = make_float4(zr[0], zr[1], zr[2], zr[3]);

    #pragma unroll
    for (int o = 16; o; o >>= 1) wm = fmaxf(wm, __shfl_xor_sync(0xffffffffu, wm, o));
    int lane = threadIdx.x & 31, w = threadIdx.x >> 5;
    if (lane == 0) sMax[w] = wm;
    __syncthreads();
    if (threadIdx.x == 0) {
        float bm = sMax[0];
        #pragma unroll
        for (int k = 1; k < 8; k++) bm = fmaxf(bm, sMax[k]);
        atomicMax(&d_slots[maxIdx], __float_as_uint(bm));
    }
}

// Final: out[c,b,g] = Z[c,bq,g,lane] * scale(slot5), tiled transpose for coalescing.
__global__ void final_kernel(float* __restrict__ out) {
    __shared__ float tile[32][33];
    const int c = blockIdx.z, bq = blockIdx.y;
    const int g0 = blockIdx.x * 32;
    const int lane = threadIdx.x, ty = threadIdx.y;   // block (32, 8)
    const float sc = slot_scale(5);
    #pragma unroll
    for (int r = 0; r < 4; r++) {
        int gi = ty + r * 8;
        tile[gi][lane] = d_Z[((c * NBQ + bq) * NG + g0 + gi) * 32 + lane];
    }
    __syncthreads();
    #pragma unroll
    for (int r = 0; r < 4; r++) {
        int bl = ty + r * 8;
        out[(c * NB + bq * 32 + bl) * NG + g0 + lane] = tile[lane][bl] * sc;
    }
}

extern "C" void kernel_launch(void* const* d_in, const int* in_sizes, int n_in,
                              void* d_out, int out_size) {
    const float* x = (const float*)d_in[0];
    const int* I = (const int*)d_in[1];
    if (in_sizes[0] != BGTOT) {   // defensive: metadata order swap
        x = (const float*)d_in[1];
        I = (const int*)d_in[0];
    }
    float* out = (float*)d_out;

    // Launch order matters for ncu (-s 5 -c 1 captures launch #6 = step-1 kernelA).
    zero_kernel<<<1, 32>>>();                                 // #1
    pack_kernel<<<(NIDX / 2 + 255) / 256, 256>>>(I);          // #2
    init_kernel<<<dim3(NG / 32, NBQ), dim3(32, 8)>>>(x);      // #3

    dim3 gA(NG / GPB, NBQ, NC);          // 32 x 4 x 4 = 512 blocks
    dim3 gB(NTOT / 1024);                // 1024 blocks, 4 elems/thread

    // step 0: R = x (broadcast over c)
    kernelA<<<gA, 256>>>(0, -1, 0);                           // #4
    kernelB<<<gB, 256>>>(0, -1, 0, 1);                        // #5
    // step 1
    kernelA<<<gA, 256>>>(1, 1, 2);                            // #6  <- ncu captures
    kernelB<<<gB, 256>>>(1, 1, 2, 3);
    // step 2
    kernelA<<<gA, 256>>>(1, 3, 4);
    kernelB<<<gB, 256>>>(1, 3, 4, 5);

    final_kernel<<<dim3(NG / 32, NBQ, NC), dim3(32, 8)>>>(out);
}

// round 13
// speedup vs baseline: 1.5737x; 1.5737x over previous
#include <cuda_runtime.h>

// Problem constants
#define NC 4
#define NB 128
#define NG 2048
#define NS 32
#define NL 3
#define NBQ 4                 // 128 b-lanes split into 4 groups of 32
#define GPB 32                // g per block in kernel A
#define NWARPS 8
#define GPW (GPB/NWARPS)      // 4 g per warp
#define NTOT (NC*NB*NG)       // 1,048,576
#define BGTOT (NB*NG)         // 262,144 (= 2^18)
#define NIDX (NC*NG*NS*NL)    // 786,432 index entries

// Scratch (no allocation allowed -> device globals)
__device__ float d_Z[NTOT];            // valuation storage (bq layout)
__device__ float d_T[NTOT];            // clause_eval output  (bq layout)
__device__ float d_xq[BGTOT];          // transposed x (bq layout, shared by all c)
__device__ unsigned d_Ioff[NIDX];      // pre-scaled byte offsets: I*128
__device__ unsigned int d_slots[8];    // float-as-uint max accumulators

__device__ __forceinline__ float slot_scale(int idx) {
    if (idx < 0) return 1.0f;
    float m = __uint_as_float(d_slots[idx]);
    return (m > 1.0f) ? (1.0f / m) : 1.0f;
}

// Launch #1: zero the max slots (kept separate so launch #6 is a step-1 kernelA for ncu).
__global__ void zero_kernel() {
    if (threadIdx.x < 8) d_slots[threadIdx.x] = 0u;
}

// Pre-scale indices to row byte offsets (idx * 32 lanes * 4B = idx << 7).
__global__ void pack_kernel(const int* __restrict__ I) {
    int i = blockIdx.x * blockDim.x + threadIdx.x;
    if (i < NIDX) d_Ioff[i] = ((unsigned)I[i]) << 7;
}

// Tiled transpose: xq[(bq*NG+g)*32 + lane] = x[(bq*32+lane)*NG + g], coalesced both ways.
__global__ void init_kernel(const float* __restrict__ x) {
    __shared__ float tile[32][33];
    const int g0 = blockIdx.x * 32, bq = blockIdx.y;
    const int lane = threadIdx.x, ty = threadIdx.y;   // block (32, 8)
    #pragma unroll
    for (int r = 0; r < 4; r++) {
        int bl = ty + r * 8;
        tile[bl][lane] = x[(bq * 32 + bl) * NG + g0 + lane];   // coalesced over g
    }
    __syncthreads();
    #pragma unroll
    for (int r = 0; r < 4; r++) {
        int gi = ty + r * 8;
        d_xq[(bq * NG + g0 + gi) * 32 + lane] = tile[lane][gi]; // coalesced over lane
    }
}

// Kernel A: T[c,b,g] = gamma*logsumexp_s( prod_l R[c,b,I[c,g,s,l]] / gamma )
// Online (chunked) logsumexp; byte-offset indices (no unpack, minimal addr math).
__global__ void __launch_bounds__(256, 6) kernelA(int srcIsZ, int scaleIdx, int maxIdx) {
    __shared__ uint4 sIdx[GPB * 24];      // 32 g * 96 offsets * 4B = 12KB
    __shared__ float sMax[NWARPS];
    const int c = blockIdx.z, bq = blockIdx.y;
    const int g0 = blockIdx.x * GPB;
    const int tid = threadIdx.x, lane = tid & 31, w = tid >> 5;

    // Stage this block's byte-offset tile (coalesced uint4) into shared
    const uint4* Ibase = (const uint4*)(d_Ioff + (c * NG + g0) * (NS * NL));
    #pragma unroll
    for (int i = tid; i < GPB * 24; i += 256) sIdx[i] = Ibase[i];
    __syncthreads();

    const float s = slot_scale(scaleIdx);
    const float s3 = s * s * s;                  // scale folded into 3-way product
    const float c2 = s3 * 144.269504f;           // (1/gamma)*s3*log2(e)
    const float* __restrict__ slab =
        srcIsZ ? (d_Z + (c * NBQ + bq) * (NG * 32)) : (d_xq + bq * (NG * 32));
    const char* __restrict__ slabL = (const char*)slab + (lane << 2);

    float wmax = 0.0f;
    #pragma unroll 1
    for (int gi = 0; gi < GPW; gi++) {
        const int gl = w * GPW + gi;
        const uint4* ip4 = sIdx + gl * 24;
        float m = 0.0f, ssum = 0.0f;             // online LSE state (products >= 0)
        #pragma unroll 1
        for (int ch = 0; ch < 4; ch++) {         // 8 substitutions per chunk
            uint4 q0 = ip4[ch * 6 + 0];
            uint4 q1 = ip4[ch * 6 + 1];
            uint4 q2 = ip4[ch * 6 + 2];
            uint4 q3 = ip4[ch * 6 + 3];
            uint4 q4 = ip4[ch * 6 + 4];
            uint4 q5 = ip4[ch * 6 + 5];
            unsigned o[24] = {q0.x, q0.y, q0.z, q0.w, q1.x, q1.y, q1.z, q1.w,
                              q2.x, q2.y, q2.z, q2.w, q3.x, q3.y, q3.z, q3.w,
                              q4.x, q4.y, q4.z, q4.w, q5.x, q5.y, q5.z, q5.w};
            float p[8];
            float cmax = 0.0f;
            #pragma unroll
            for (int j = 0; j < 8; j++) {
                float v0 = *(const float*)(slabL + o[3 * j + 0]);  // 128B coalesced
                float v1 = *(const float*)(slabL + o[3 * j + 1]);
                float v2 = *(const float*)(slabL + o[3 * j + 2]);
                float pp = v0 * v1 * v2;
                p[j] = pp;
                cmax = fmaxf(cmax, pp);
            }
            float mn = fmaxf(m, cmax);
            float acc = ssum * exp2f((m - mn) * c2);
            float e0 = exp2f((p[0] - mn) * c2) + exp2f((p[1] - mn) * c2);
            float e1 = exp2f((p[2] - mn) * c2) + exp2f((p[3] - mn) * c2);
            float e2 = exp2f((p[4] - mn) * c2) + exp2f((p[5] - mn) * c2);
            float e3 = exp2f((p[6] - mn) * c2) + exp2f((p[7] - mn) * c2);
            ssum = acc + ((e0 + e1) + (e2 + e3));
            m = mn;
        }
        float t = fmaf(0.0069314718f, __log2f(ssum), m * s3);   // gamma*ln2*log2
        d_T[((c * NBQ + bq) * NG + g0 + gl) * 32 + lane] = t;
        wmax = fmaxf(wmax, t);
    }
    #pragma unroll
    for (int o = 16; o; o >>= 1) wmax = fmaxf(wmax, __shfl_xor_sync(0xffffffffu, wmax, o));
    if (lane == 0) sMax[w] = wmax;
    __syncthreads();
    if (tid == 0) {
        float bm = sMax[0];
        #pragma unroll
        for (int k = 1; k < NWARPS; k++) bm = fmaxf(bm, sMax[k]);
        atomicMax(&d_slots[maxIdx], __float_as_uint(bm));
    }
}

// Kernel B: Z = softor2(R, T') elementwise, 4 elems/thread via float4.
__global__ void __launch_bounds__(256) kernelB(int srcIsZ, int rIdx, int tIdx, int maxIdx) {
    __shared__ float sMax[8];
    const int i = blockIdx.x * 256 + threadIdx.x;        // float4 index
    const float sr = slot_scale(rIdx);
    const float st = slot_scale(tIdx);
    float4 rv = srcIsZ ? ((const float4*)d_Z)[i]
                       : ((const float4*)d_xq)[i & (BGTOT / 4 - 1)];
    float4 tv = ((const float4*)d_T)[i];
    float zr[4];
    const float r4[4] = {rv.x, rv.y, rv.z, rv.w};
    const float t4[4] = {tv.x, tv.y, tv.z, tv.w};
    float wm = 0.0f;
    #pragma unroll
    for (int j = 0; j < 4; j++) {
        float r = r4[j] * sr, t = t4[j] * st;
        float mx = fmaxf(r, t), mn = fminf(r, t);
        float z = fmaf(0.0069314718f,
                       __log2f(1.0f + exp2f((mn - mx) * 144.269504f)), mx);
        zr[j] = z;
        wm = fmaxf(wm, z);
    }
    ((float4*)d_Z)[i] = make_float4(zr[0], zr[1], zr[2], zr[3]);

    #pragma unroll
    for (int o = 16; o; o >>= 1) wm = fmaxf(wm, __shfl_xor_sync(0xffffffffu, wm, o));
    int lane = threadIdx.x & 31, w = threadIdx.x >> 5;
    if (lane == 0) sMax[w] = wm;
    __syncthreads();
    if (threadIdx.x == 0) {
        float bm = sMax[0];
        #pragma unroll
        for (int k = 1; k < 8; k++) bm = fmaxf(bm, sMax[k]);
        atomicMax(&d_slots[maxIdx], __float_as_uint(bm));
    }
}

// Final: out[c,b,g] = Z[c,bq,g,lane] * scale(slot5), tiled transpose for coalescing.
__global__ void final_kernel(float* __restrict__ out) {
    __shared__ float tile[32][33];
    const int c = blockIdx.z, bq = blockIdx.y;
    const int g0 = blockIdx.x * 32;
    const int lane = threadIdx.x, ty = threadIdx.y;   // block (32, 8)
    const float sc = slot_scale(5);
    #pragma unroll
    for (int r = 0; r < 4; r++) {
        int gi = ty + r * 8;
        tile[gi][lane] = d_Z[((c * NBQ + bq) * NG + g0 + gi) * 32 + lane];
    }
    __syncthreads();
    #pragma unroll
    for (int r = 0; r < 4; r++) {
        int bl = ty + r * 8;
        out[(c * NB + bq * 32 + bl) * NG + g0 + lane] = tile[lane][bl] * sc;
    }
}

extern "C" void kernel_launch(void* const* d_in, const int* in_sizes, int n_in,
                              void* d_out, int out_size) {
    const float* x = (const float*)d_in[0];
    const int* I = (const int*)d_in[1];
    if (in_sizes[0] != BGTOT) {   // defensive: metadata order swap
        x = (const float*)d_in[1];
        I = (const int*)d_in[0];
    }
    float* out = (float*)d_out;

    // Launch order matters for ncu (-s 5 -c 1 captures launch #6 = step-1 kernelA).
    zero_kernel<<<1, 32>>>();                                 // #1
    pack_kernel<<<(NIDX + 255) / 256, 256>>>(I);              // #2
    init_kernel<<<dim3(NG / 32, NBQ), dim3(32, 8)>>>(x);      // #3

    dim3 gA(NG / GPB, NBQ, NC);          // 64 x 4 x 4 = 1024 blocks
    dim3 gB(NTOT / 1024);                // 1024 blocks, 4 elems/thread

    // step 0: R = x (broadcast over c)
    kernelA<<<gA, 256>>>(0, -1, 0);                           // #4
    kernelB<<<gB, 256>>>(0, -1, 0, 1);                        // #5
    // step 1
    kernelA<<<gA, 256>>>(1, 1, 2);                            // #6  <- ncu captures
    kernelB<<<gB, 256>>>(1, 1, 2, 3);
    // step 2
    kernelA<<<gA, 256>>>(1, 3, 4);
    kernelB<<<gB, 256>>>(1, 3, 4, 5);

    final_kernel<<<dim3(NG / 32, NBQ, NC), dim3(32, 8)>>>(out);
}

// round 16
// speedup vs baseline: 1.7124x; 1.0881x over previous
#include <cuda_runtime.h>

// Problem constants
#define NC 4
#define NB 128
#define NG 2048
#define NS 32
#define NL 3
#define NBQ2 2                // 128 b-lanes split into 2 groups of 64 (float2 per thread)
#define GPB 16                // g per block in kernel A
#define NWARPS 8
#define GPW (GPB/NWARPS)      // 2 g per warp
#define NTOT (NC*NB*NG)       // 1,048,576
#define BGTOT (NB*NG)         // 262,144 (= 2^18)
#define NIDX (NC*NG*NS*NL)    // 786,432 index entries

// Scratch (no allocation allowed -> device globals)
__device__ float d_Z[NTOT];            // valuation storage (bq2 layout: [c][bq2][g][64])
__device__ float d_T[NTOT];            // clause_eval output  (bq2 layout)
__device__ float d_xq[BGTOT];          // transposed x (bq2 layout, shared by all c)
__device__ unsigned d_Ioff[NIDX];      // pre-scaled byte offsets: I*256 (64 floats/row)
__device__ unsigned int d_slots[8];    // float-as-uint max accumulators

typedef unsigned long long ull;

__device__ __forceinline__ float slot_scale(int idx) {
    if (idx < 0) return 1.0f;
    float m = __uint_as_float(d_slots[idx]);
    return (m > 1.0f) ? (1.0f / m) : 1.0f;
}

// Packed f32x2 multiply (Blackwell dual-FMA pipe; only reachable via PTX).
__device__ __forceinline__ ull mul2(ull a, ull b) {
    ull r; asm("mul.rn.f32x2 %0, %1, %2;" : "=l"(r) : "l"(a), "l"(b)); return r;
}
__device__ __forceinline__ float lo2(ull v) { return __uint_as_float((unsigned)v); }
__device__ __forceinline__ float hi2(ull v) { return __uint_as_float((unsigned)(v >> 32)); }

// Launch #1: zero the max slots (kept separate so launch #6 is a step-1 kernelA for ncu).
__global__ void zero_kernel() {
    if (threadIdx.x < 8) d_slots[threadIdx.x] = 0u;
}

// Pre-scale indices to row byte offsets (idx * 64 lanes * 4B = idx << 8).
__global__ void pack_kernel(const int* __restrict__ I) {
    int i = blockIdx.x * blockDim.x + threadIdx.x;
    if (i < NIDX) d_Ioff[i] = ((unsigned)I[i]) << 8;
}

// Tiled transpose: xq[(bq2*NG+g)*64 + b2] = x[(bq2*64+b2)*NG + g], coalesced both ways.
__global__ void init_kernel(const float* __restrict__ x) {
    __shared__ float tile[64][33];
    const int g0 = blockIdx.x * 32, bq2 = blockIdx.y;
    const int lane = threadIdx.x, ty = threadIdx.y;   // block (32, 8)
    #pragma unroll
    for (int r = 0; r < 8; r++) {
        int bl = ty + r * 8;                            // 64 b rows
        tile[bl][lane] = x[(bq2 * 64 + bl) * NG + g0 + lane];  // coalesced over g
    }
    __syncthreads();
    #pragma unroll
    for (int r = 0; r < 4; r++) {
        int gi = ty + r * 8;                            // 32 g rows
        float2 v = make_float2(tile[lane * 2][gi], tile[lane * 2 + 1][gi]);
        ((float2*)d_xq)[((bq2 * NG + g0 + gi) * 64 >> 1) + lane] = v;  // 256B coalesced
    }
}

// Kernel A: T[c,b,g] = gamma*logsumexp_s( prod_l R[c,b,I[c,g,s,l]] / gamma )
// float2 over b: LDG.64 gathers + packed f32x2 products; online LSE in chunks of 4.
__global__ void __launch_bounds__(256, 6) kernelA(int srcIsZ, int scaleIdx, int maxIdx) {
    __shared__ uint4 sIdx[GPB * 24];      // 16 g * 96 offsets * 4B = 6KB
    __shared__ float sMax[NWARPS];
    const int c = blockIdx.z, bq2 = blockIdx.y;
    const int g0 = blockIdx.x * GPB;
    const int tid = threadIdx.x, lane = tid & 31, w = tid >> 5;

    // Stage this block's byte-offset tile (coalesced uint4) into shared
    const uint4* Ibase = (const uint4*)(d_Ioff + (c * NG + g0) * (NS * NL));
    #pragma unroll
    for (int i = tid; i < GPB * 24; i += 256) sIdx[i] = Ibase[i];
    __syncthreads();

    const float s = slot_scale(scaleIdx);
    const float s3 = s * s * s;                  // scale folded into 3-way product
    const float c2 = s3 * 144.269504f;           // (1/gamma)*s3*log2(e)
    const float* __restrict__ slab =
        srcIsZ ? (d_Z + (c * NBQ2 + bq2) * (NG * 64)) : (d_xq + bq2 * (NG * 64));
    const char* __restrict__ slabL = (const char*)slab + (lane << 3);  // float2 lane

    float wmax = 0.0f;
    #pragma unroll 1
    for (int gi = 0; gi < GPW; gi++) {
        const int gl = w * GPW + gi;
        const uint4* ip4 = sIdx + gl * 24;
        float mx = 0.0f, my = 0.0f, sx = 0.0f, sy = 0.0f;   // online LSE (products >= 0)
        #pragma unroll 1
        for (int ch = 0; ch < 8; ch++) {          // 4 substitutions per chunk
            uint4 q0 = ip4[ch * 3 + 0];           // 12 offsets = 4 s * 3 l
            uint4 q1 = ip4[ch * 3 + 1];
            uint4 q2 = ip4[ch * 3 + 2];
            ull p0, p1, p2, p3;
            {
                ull a = *(const ull*)(slabL + q0.x);
                ull b = *(const ull*)(slabL + q0.y);
                ull d = *(const ull*)(slabL + q0.z);
                p0 = mul2(mul2(a, b), d);
            }
            {
                ull a = *(const ull*)(slabL + q0.w);
                ull b = *(const ull*)(slabL + q1.x);
                ull d = *(const ull*)(slabL + q1.y);
                p1 = mul2(mul2(a, b), d);
            }
            {
                ull a = *(const ull*)(slabL + q1.z);
                ull b = *(const ull*)(slabL + q1.w);
                ull d = *(const ull*)(slabL + q2.x);
                p2 = mul2(mul2(a, b), d);
            }
            {
                ull a = *(const ull*)(slabL + q2.y);
                ull b = *(const ull*)(slabL + q2.z);
                ull d = *(const ull*)(slabL + q2.w);
                p3 = mul2(mul2(a, b), d);
            }
            float cx = fmaxf(fmaxf(lo2(p0), lo2(p1)), fmaxf(lo2(p2), lo2(p3)));
            float cy = fmaxf(fmaxf(hi2(p0), hi2(p1)), fmaxf(hi2(p2), hi2(p3)));
            float mnx = fmaxf(mx, cx), mny = fmaxf(my, cy);
            float bx = mnx * c2, by = mny * c2;
            float ax = sx * exp2f(fmaf(mx, c2, -bx));
            float ay = sy * exp2f(fmaf(my, c2, -by));
            sx = ax + ((exp2f(fmaf(lo2(p0), c2, -bx)) + exp2f(fmaf(lo2(p1), c2, -bx)))
                     + (exp2f(fmaf(lo2(p2), c2, -bx)) + exp2f(fmaf(lo2(p3), c2, -bx))));
            sy = ay + ((exp2f(fmaf(hi2(p0), c2, -by)) + exp2f(fmaf(hi2(p1), c2, -by)))
                     + (exp2f(fmaf(hi2(p2), c2, -by)) + exp2f(fmaf(hi2(p3), c2, -by))));
            mx = mnx; my = mny;
        }
        float tx = fmaf(0.0069314718f, __log2f(sx), mx * s3);   // gamma*ln2*log2
        float ty = fmaf(0.0069314718f, __log2f(sy), my * s3);
        ((float2*)d_T)[(((c * NBQ2 + bq2) * NG + g0 + gl) * 64 >> 1) + lane] =
            make_float2(tx, ty);
        wmax = fmaxf(wmax, fmaxf(tx, ty));
    }
    #pragma unroll
    for (int o = 16; o; o >>= 1) wmax = fmaxf(wmax, __shfl_xor_sync(0xffffffffu, wmax, o));
    if (lane == 0) sMax[w] = wmax;
    __syncthreads();
    if (tid == 0) {
        float bm = sMax[0];
        #pragma unroll
        for (int k = 1; k < NWARPS; k++) bm = fmaxf(bm, sMax[k]);
        atomicMax(&d_slots[maxIdx], __float_as_uint(bm));
    }
}

// Kernel B: Z = softor2(R, T') elementwise, 4 elems/thread via float4 (layout-agnostic).
__global__ void __launch_bounds__(256) kernelB(int srcIsZ, int rIdx, int tIdx, int maxIdx) {
    __shared__ float sMax[8];
    const int i = blockIdx.x * 256 + threadIdx.x;        // float4 index
    const float sr = slot_scale(rIdx);
    const float st = slot_scale(tIdx);
    float4 rv = srcIsZ ? ((const float4*)d_Z)[i]
                       : ((const float4*)d_xq)[i & (BGTOT / 4 - 1)];
    float4 tv = ((const float4*)d_T)[i];
    float zr[4];
    const float r4[4] = {rv.x, rv.y, rv.z, rv.w};
    const float t4[4] = {tv.x, tv.y, tv.z, tv.w};
    float wm = 0.0f;
    #pragma unroll
    for (int j = 0; j < 4; j++) {
        float r = r4[j] * sr, t = t4[j] * st;
        float mx = fmaxf(r, t), mn = fminf(r, t);
        float z = fmaf(0.0069314718f,
                       __log2f(1.0f + exp2f((mn - mx) * 144.269504f)), mx);
        zr[j] = z;
        wm = fmaxf(wm, z);
    }
    ((float4*)d_Z)[i] = make_float4(zr[0], zr[1], zr[2], zr[3]);

    #pragma unroll
    for (int o = 16; o; o >>= 1) wm = fmaxf(wm, __shfl_xor_sync(0xffffffffu, wm, o));
    int lane = threadIdx.x & 31, w = threadIdx.x >> 5;
    if (lane == 0) sMax[w] = wm;
    __syncthreads();
    if (threadIdx.x == 0) {
        float bm = sMax[0];
        #pragma unroll
        for (int k = 1; k < 8; k++) bm = fmaxf(bm, sMax[k]);
        atomicMax(&d_slots[maxIdx], __float_as_uint(bm));
    }
}

// Final: out[c, bq2*64+b2, g] = Z[c,bq2,g,b2] * scale(slot5), tiled transpose.
__global__ void final_kernel(float* __restrict__ out) {
    __shared__ float2 tile[32][33];
    const int c = blockIdx.z, bq2 = blockIdx.y;
    const int g0 = blockIdx.x * 32;
    const int lane = threadIdx.x, ty = threadIdx.y;   // block (32, 8)
    const float sc = slot_scale(5);
    #pragma unroll
    for (int r = 0; r < 4; r++) {
        int gi = ty + r * 8;
        tile[gi][lane] =
            ((const float2*)d_Z)[(((c * NBQ2 + bq2) * NG + g0 + gi) * 64 >> 1) + lane];
    }
    __syncthreads();
    #pragma unroll
    for (int r = 0; r < 8; r++) {
        int bl = ty + r * 8;                           // 64 b rows
        float2 v = tile[lane][bl >> 1];
        float val = (bl & 1) ? v.y : v.x;
        out[(c * NB + bq2 * 64 + bl) * NG + g0 + lane] = val * sc;
    }
}

extern "C" void kernel_launch(void* const* d_in, const int* in_sizes, int n_in,
                              void* d_out, int out_size) {
    const float* x = (const float*)d_in[0];
    const int* I = (const int*)d_in[1];
    if (in_sizes[0] != BGTOT) {   // defensive: metadata order swap
        x = (const float*)d_in[1];
        I = (const int*)d_in[0];
    }
    float* out = (float*)d_out;

    // Launch order matters for ncu (-s 5 -c 1 captures launch #6 = step-1 kernelA).
    zero_kernel<<<1, 32>>>();                                 // #1
    pack_kernel<<<(NIDX + 255) / 256, 256>>>(I);              // #2
    init_kernel<<<dim3(NG / 32, NBQ2), dim3(32, 8)>>>(x);     // #3

    dim3 gA(NG / GPB, NBQ2, NC);         // 128 x 2 x 4 = 1024 blocks
    dim3 gB(NTOT / 1024);                // 1024 blocks, 4 elems/thread

    // step 0: R = x (broadcast over c)
    kernelA<<<gA, 256>>>(0, -1, 0);                           // #4
    kernelB<<<gB, 256>>>(0, -1, 0, 1);                        // #5
    // step 1
    kernelA<<<gA, 256>>>(1, 1, 2);                            // #6  <- ncu captures
    kernelB<<<gB, 256>>>(1, 1, 2, 3);
    // step 2
    kernelA<<<gA, 256>>>(1, 3, 4);
    kernelB<<<gB, 256>>>(1, 3, 4, 5);

    final_kernel<<<dim3(NG / 32, NBQ2, NC), dim3(32, 8)>>>(out);
}

// round 17
// speedup vs baseline: 1.8757x; 1.0954x over previous
#include <cuda_runtime.h>

// Problem constants
#define NC 4
#define NB 128
#define NG 2048
#define NS 32
#define NL 3
#define GPB 8                 // g per block in kernel A (8 warps, 1 g per warp)
#define NWARPS 8
#define NTOT (NC*NB*NG)       // 1,048,576
#define BGTOT (NB*NG)         // 262,144 (= 2^18)
#define NIDX (NC*NG*NS*NL)    // 786,432 index entries

// Scratch (no allocation allowed -> device globals)
// Layout: [c][g][128 b] (rows of 128 floats = 512B)
__device__ float d_Z[NTOT];
__device__ float d_T[NTOT];
__device__ float d_xq[BGTOT];          // [g][128 b], shared by all c
__device__ unsigned d_Ioff[NIDX];      // pre-scaled byte offsets: I*512
__device__ unsigned int d_slots[8];    // float-as-uint max accumulators

typedef unsigned long long ull;

__device__ __forceinline__ float slot_scale(int idx) {
    if (idx < 0) return 1.0f;
    float m = __uint_as_float(d_slots[idx]);
    return (m > 1.0f) ? (1.0f / m) : 1.0f;
}

// Packed f32x2 ops (Blackwell dual-FMA pipe; only reachable via PTX).
__device__ __forceinline__ ull mul2(ull a, ull b) {
    ull r; asm("mul.rn.f32x2 %0, %1, %2;" : "=l"(r) : "l"(a), "l"(b)); return r;
}
__device__ __forceinline__ ull fma2(ull a, ull b, ull c) {
    ull r; asm("fma.rn.f32x2 %0, %1, %2, %3;" : "=l"(r) : "l"(a), "l"(b), "l"(c)); return r;
}
__device__ __forceinline__ ull pack2(float x, float y) {
    ull r; asm("mov.b64 %0, {%1, %2};" : "=l"(r) : "f"(x), "f"(y)); return r;
}
__device__ __forceinline__ float lo2(ull v) { return __uint_as_float((unsigned)v); }
__device__ __forceinline__ float hi2(ull v) { return __uint_as_float((unsigned)(v >> 32)); }

// Launch #1: zero the max slots (kept separate so launch #6 is a step-1 kernelA for ncu).
__global__ void zero_kernel() {
    if (threadIdx.x < 8) d_slots[threadIdx.x] = 0u;
}

// Pre-scale indices to row byte offsets (idx * 128 lanes * 4B = idx << 9).
__global__ void pack_kernel(const int* __restrict__ I) {
    int i = blockIdx.x * blockDim.x + threadIdx.x;
    if (i < NIDX) d_Ioff[i] = ((unsigned)I[i]) << 9;
}

// Tiled transpose: xq[g][b] = x[b][g], coalesced both ways (float4 stores).
__global__ void init_kernel(const float* __restrict__ x) {
    __shared__ float tile[128][33];
    const int g0 = blockIdx.x * 32;
    const int lane = threadIdx.x, ty = threadIdx.y;   // block (32, 8)
    #pragma unroll
    for (int r = 0; r < 16; r++) {
        int bl = ty + r * 8;                           // 128 b rows
        tile[bl][lane] = x[bl * NG + g0 + lane];       // coalesced over g
    }
    __syncthreads();
    #pragma unroll
    for (int r = 0; r < 4; r++) {
        int gi = ty + r * 8;
        float4 v = make_float4(tile[lane * 4 + 0][gi], tile[lane * 4 + 1][gi],
                               tile[lane * 4 + 2][gi], tile[lane * 4 + 3][gi]);
        ((float4*)d_xq)[(g0 + gi) * 32 + lane] = v;    // 512B coalesced rows
    }
}

// Kernel A: T[c,b,g] = gamma*logsumexp_s( prod_l R[c,b,I[c,g,s,l]] / gamma )
// float4 over b: LDG.128 gathers + packed f32x2 products/args; online LSE, chunks of 4.
__global__ void __launch_bounds__(256, 5) kernelA(int srcIsZ, int scaleIdx, int maxIdx) {
    __shared__ uint4 sIdx[GPB * 24];      // 8 g * 96 offsets * 4B = 3KB
    __shared__ float sMax[NWARPS];
    const int c = blockIdx.y;
    const int g0 = blockIdx.x * GPB;
    const int tid = threadIdx.x, lane = tid & 31, w = tid >> 5;

    // Stage this block's byte-offset tile (coalesced uint4) into shared
    const uint4* Ibase = (const uint4*)(d_Ioff + (c * NG + g0) * (NS * NL));
    if (tid < GPB * 24) sIdx[tid] = Ibase[tid];
    __syncthreads();

    const float s = slot_scale(scaleIdx);
    const float s3 = s * s * s;                  // scale folded into 3-way product
    const float K2 = s3 * 144.269504f;           // (1/gamma)*s3*log2(e)
    const float nK2 = -K2;
    const ull K2p = pack2(K2, K2);
    const float* __restrict__ slab = srcIsZ ? (d_Z + c * (NG * 128)) : d_xq;
    const char* __restrict__ slabL = (const char*)slab + (lane << 4);  // float4 lane

    const int g = g0 + w;                        // one g per warp
    const uint4* ip4 = sIdx + w * 24;

    float m0 = 0.f, m1 = 0.f, m2 = 0.f, m3 = 0.f;    // online LSE (products >= 0)
    float s0 = 0.f, s1 = 0.f, s2 = 0.f, s3s = 0.f;
    #pragma unroll 1
    for (int ch = 0; ch < 8; ch++) {             // 4 substitutions per chunk
        uint4 q0 = ip4[ch * 3 + 0];
        uint4 q1 = ip4[ch * 3 + 1];
        uint4 q2 = ip4[ch * 3 + 2];
        ulonglong2 a0 = *(const ulonglong2*)(slabL + q0.x);
        ulonglong2 b0 = *(const ulonglong2*)(slabL + q0.y);
        ulonglong2 d0 = *(const ulonglong2*)(slabL + q0.z);
        ulonglong2 a1 = *(const ulonglong2*)(slabL + q0.w);
        ulonglong2 b1 = *(const ulonglong2*)(slabL + q1.x);
        ulonglong2 d1 = *(const ulonglong2*)(slabL + q1.y);
        ulonglong2 a2 = *(const ulonglong2*)(slabL + q1.z);
        ulonglong2 b2 = *(const ulonglong2*)(slabL + q1.w);
        ulonglong2 d2 = *(const ulonglong2*)(slabL + q2.x);
        ulonglong2 a3 = *(const ulonglong2*)(slabL + q2.y);
        ulonglong2 b3 = *(const ulonglong2*)(slabL + q2.z);
        ulonglong2 d3 = *(const ulonglong2*)(slabL + q2.w);
        ull pl0 = mul2(mul2(a0.x, b0.x), d0.x), ph0 = mul2(mul2(a0.y, b0.y), d0.y);
        ull pl1 = mul2(mul2(a1.x, b1.x), d1.x), ph1 = mul2(mul2(a1.y, b1.y), d1.y);
        ull pl2 = mul2(mul2(a2.x, b2.x), d2.x), ph2 = mul2(mul2(a2.y, b2.y), d2.y);
        ull pl3 = mul2(mul2(a3.x, b3.x), d3.x), ph3 = mul2(mul2(a3.y, b3.y), d3.y);

        float c0 = fmaxf(fmaxf(lo2(pl0), lo2(pl1)), fmaxf(lo2(pl2), lo2(pl3)));
        float c1 = fmaxf(fmaxf(hi2(pl0), hi2(pl1)), fmaxf(hi2(pl2), hi2(pl3)));
        float cc2 = fmaxf(fmaxf(lo2(ph0), lo2(ph1)), fmaxf(lo2(ph2), lo2(ph3)));
        float c3 = fmaxf(fmaxf(hi2(ph0), hi2(ph1)), fmaxf(hi2(ph2), hi2(ph3)));
        float n0 = fmaxf(m0, c0), n1 = fmaxf(m1, c1);
        float n2 = fmaxf(m2, cc2), n3 = fmaxf(m3, c3);
        float t0 = n0 * nK2, t1 = n1 * nK2, t2 = n2 * nK2, t3 = n3 * nK2;
        ull nb01 = pack2(t0, t1), nb23 = pack2(t2, t3);

        // rescale old sums: exp2((m - n)*K2)
        float r0 = exp2f(fmaf(m0, K2, t0));
        float r1 = exp2f(fmaf(m1, K2, t1));
        float r2 = exp2f(fmaf(m2, K2, t2));
        float r3 = exp2f(fmaf(m3, K2, t3));

        ull e0 = fma2(pl0, K2p, nb01), e1 = fma2(pl1, K2p, nb01);
        ull e2 = fma2(pl2, K2p, nb01), e3 = fma2(pl3, K2p, nb01);
        ull f0 = fma2(ph0, K2p, nb23), f1 = fma2(ph1, K2p, nb23);
        ull f2 = fma2(ph2, K2p, nb23), f3 = fma2(ph3, K2p, nb23);
        float u0 = (exp2f(lo2(e0)) + exp2f(lo2(e1))) + (exp2f(lo2(e2)) + exp2f(lo2(e3)));
        float u1 = (exp2f(hi2(e0)) + exp2f(hi2(e1))) + (exp2f(hi2(e2)) + exp2f(hi2(e3)));
        float u2 = (exp2f(lo2(f0)) + exp2f(lo2(f1))) + (exp2f(lo2(f2)) + exp2f(lo2(f3)));
        float u3 = (exp2f(hi2(f0)) + exp2f(hi2(f1))) + (exp2f(hi2(f2)) + exp2f(hi2(f3)));
        s0 = fmaf(s0, r0, u0); s1 = fmaf(s1, r1, u1);
        s2 = fmaf(s2, r2, u2); s3s = fmaf(s3s, r3, u3);
        m0 = n0; m1 = n1; m2 = n2; m3 = n3;
    }
    float t0 = fmaf(0.0069314718f, __log2f(s0), m0 * s3);   // gamma*ln2*log2
    float t1 = fmaf(0.0069314718f, __log2f(s1), m1 * s3);
    float t2 = fmaf(0.0069314718f, __log2f(s2), m2 * s3);
    float t3 = fmaf(0.0069314718f, __log2f(s3s), m3 * s3);
    ((float4*)d_T)[(c * NG + g) * 32 + lane] = make_float4(t0, t1, t2, t3);

    float wmax = fmaxf(fmaxf(t0, t1), fmaxf(t2, t3));
    #pragma unroll
    for (int o = 16; o; o >>= 1) wmax = fmaxf(wmax, __shfl_xor_sync(0xffffffffu, wmax, o));
    if (lane == 0) sMax[w] = wmax;
    __syncthreads();
    if (tid == 0) {
        float bm = sMax[0];
        #pragma unroll
        for (int k = 1; k < NWARPS; k++) bm = fmaxf(bm, sMax[k]);
        atomicMax(&d_slots[maxIdx], __float_as_uint(bm));
    }
}

// Kernel B: Z = softor2(R, T') elementwise, 4 elems/thread via float4 (layout-agnostic).
__global__ void __launch_bounds__(256) kernelB(int srcIsZ, int rIdx, int tIdx, int maxIdx) {
    __shared__ float sMax[8];
    const int i = blockIdx.x * 256 + threadIdx.x;        // float4 index
    const float sr = slot_scale(rIdx);
    const float st = slot_scale(tIdx);
    float4 rv = srcIsZ ? ((const float4*)d_Z)[i]
                       : ((const float4*)d_xq)[i & (BGTOT / 4 - 1)];
    float4 tv = ((const float4*)d_T)[i];
    float zr[4];
    const float r4[4] = {rv.x, rv.y, rv.z, rv.w};
    const float t4[4] = {tv.x, tv.y, tv.z, tv.w};
    float wm = 0.0f;
    #pragma unroll
    for (int j = 0; j < 4; j++) {
        float r = r4[j] * sr, t = t4[j] * st;
        float mx = fmaxf(r, t), mn = fminf(r, t);
        float z = fmaf(0.0069314718f,
                       __log2f(1.0f + exp2f((mn - mx) * 144.269504f)), mx);
        zr[j] = z;
        wm = fmaxf(wm, z);
    }
    ((float4*)d_Z)[i] = make_float4(zr[0], zr[1], zr[2], zr[3]);

    #pragma unroll
    for (int o = 16; o; o >>= 1) wm = fmaxf(wm, __shfl_xor_sync(0xffffffffu, wm, o));
    int lane = threadIdx.x & 31, w = threadIdx.x >> 5;
    if (lane == 0) sMax[w] = wm;
    __syncthreads();
    if (threadIdx.x == 0) {
        float bm = sMax[0];
        #pragma unroll
        for (int k = 1; k < 8; k++) bm = fmaxf(bm, sMax[k]);
        atomicMax(&d_slots[maxIdx], __float_as_uint(bm));
    }
}

// Final: out[c][b][g] = Z[c][g][b] * scale(slot5), tiled transpose for coalescing.
__global__ void final_kernel(float* __restrict__ out) {
    __shared__ float tile[32][129];
    const int c = blockIdx.y;
    const int g0 = blockIdx.x * 32;
    const int lane = threadIdx.x, ty = threadIdx.y;   // block (32, 8)
    const float sc = slot_scale(5);
    #pragma unroll
    for (int r = 0; r < 4; r++) {
        int gi = ty + r * 8;
        float4 v = ((const float4*)d_Z)[(c * NG + g0 + gi) * 32 + lane];
        tile[gi][lane * 4 + 0] = v.x;
        tile[gi][lane * 4 + 1] = v.y;
        tile[gi][lane * 4 + 2] = v.z;
        tile[gi][lane * 4 + 3] = v.w;
    }
    __syncthreads();
    #pragma unroll
    for (int r = 0; r < 16; r++) {
        int bl = ty + r * 8;                          // 128 b rows
        out[(c * NB + bl) * NG + g0 + lane] = tile[lane][bl] * sc;
    }
}

extern "C" void kernel_launch(void* const* d_in, const int* in_sizes, int n_in,
                              void* d_out, int out_size) {
    const float* x = (const float*)d_in[0];
    const int* I = (const int*)d_in[1];
    if (in_sizes[0] != BGTOT) {   // defensive: metadata order swap
        x = (const float*)d_in[1];
        I = (const int*)d_in[0];
    }
    float* out = (float*)d_out;

    // Launch order matters for ncu (-s 5 -c 1 captures launch #6 = step-1 kernelA).
    zero_kernel<<<1, 32>>>();                                 // #1
    pack_kernel<<<(NIDX + 255) / 256, 256>>>(I);              // #2
    init_kernel<<<dim3(NG / 32, 1), dim3(32, 8)>>>(x);        // #3

    dim3 gA(NG / GPB, NC);               // 256 x 4 = 1024 blocks
    dim3 gB(NTOT / 1024);                // 1024 blocks, 4 elems/thread

    // step 0: R = x (broadcast over c)
    kernelA<<<gA, 256>>>(0, -1, 0);                           // #4
    kernelB<<<gB, 256>>>(0, -1, 0, 1);                        // #5
    // step 1
    kernelA<<<gA, 256>>>(1, 1, 2);                            // #6  <- ncu captures
    kernelB<<<gB, 256>>>(1, 1, 2, 3);
    // step 2
    kernelA<<<gA, 256>>>(1, 3, 4);
    kernelB<<<gB, 256>>>(1, 3, 4, 5);

    final_kernel<<<dim3(NG / 32, NC), dim3(32, 8)>>>(out);
}